// round 7
// baseline (speedup 1.0000x reference)
#include <cuda_runtime.h>
#include <cuda_bf16.h>
#include <math.h>

#define BB 8192
#define CC 512
#define NSLOT 32
#define NCH 4
#define RCH (BB / NCH)   // 2048 rows per pipeline chunk

// ---------------- scratch (no allocations allowed) ----------------
__device__ float g_WV  [BB*CC];
__device__ float g_upd [BB*CC];
__device__ float g_ww  [BB*NSLOT];
__device__ float g_etas[CC];
__device__ __nv_bfloat16 g_Qb   [BB*CC];
__device__ __nv_bfloat16 g_WKb  [BB*CC];
__device__ __nv_bfloat16 g_hb   [BB*CC];
__device__ __nv_bfloat16 g_pb   [BB*CC];
__device__ __nv_bfloat16 g_retrb[BB*CC];
__device__ __nv_bfloat16 g_Wqb  [CC*CC];
__device__ __nv_bfloat16 g_Wkb  [CC*CC];
__device__ __nv_bfloat16 g_Wvb  [CC*CC];
__device__ __nv_bfloat16 g_Wgb  [2*CC*CC];

// ---------------- helpers ----------------
__device__ __forceinline__ uint2 cvt4(float4 v) {
    __nv_bfloat162 lo = __floats2bfloat162_rn(v.x, v.y);
    __nv_bfloat162 hi = __floats2bfloat162_rn(v.z, v.w);
    uint2 r;
    r.x = *reinterpret_cast<unsigned int*>(&lo);
    r.y = *reinterpret_cast<unsigned int*>(&hi);
    return r;
}

__device__ __forceinline__ unsigned smem_u32(const void* p) {
    unsigned a;
    asm volatile("{ .reg .u64 t; cvta.to.shared.u64 t, %1; cvt.u32.u64 %0, t; }"
                 : "=r"(a) : "l"(p));
    return a;
}

__device__ __forceinline__ void cp16(unsigned dst, const void* src) {
    asm volatile("cp.async.cg.shared.global [%0], [%1], 16;" :: "r"(dst), "l"(src));
}
#define CP_COMMIT() asm volatile("cp.async.commit_group;" ::)
#define CP_WAIT1()  asm volatile("cp.async.wait_group 1;" ::)
#define CP_WAIT0()  asm volatile("cp.async.wait_group 0;" ::)

__device__ __forceinline__ void ldsm4(unsigned* r, unsigned a) {
    asm volatile("ldmatrix.sync.aligned.m8n8.x4.shared.b16 {%0,%1,%2,%3}, [%4];"
                 : "=r"(r[0]), "=r"(r[1]), "=r"(r[2]), "=r"(r[3]) : "r"(a));
}

__device__ __forceinline__ void mma16816(float* d, const unsigned* a, const unsigned* b) {
    asm volatile(
        "mma.sync.aligned.m16n8k16.row.col.f32.bf16.bf16.f32 "
        "{%0,%1,%2,%3}, {%4,%5,%6,%7}, {%8,%9}, {%0,%1,%2,%3};\n"
        : "+f"(d[0]), "+f"(d[1]), "+f"(d[2]), "+f"(d[3])
        : "r"(a[0]), "r"(a[1]), "r"(a[2]), "r"(a[3]), "r"(b[0]), "r"(b[1]));
}

// ---------------- one-shot bf16 conversion ----------------
__global__ void __launch_bounds__(256) convert_kernel(
    const float* __restrict__ h, const float* __restrict__ p,
    const float* __restrict__ Wq, const float* __restrict__ Wk,
    const float* __restrict__ Wv, const float* __restrict__ Wg,
    const float* __restrict__ eta)
{
    if (blockIdx.x == 0 && threadIdx.x < 256) {
        for (int c = threadIdx.x; c < CC; c += 256)
            g_etas[c] = 1.f / (1.f + __expf(-eta[c]));
    }
    int i = blockIdx.x * 256 + threadIdx.x;
    const float4* src; __nv_bfloat16* dst; int off;
    if      (i < 1048576) { src = (const float4*)h;  dst = g_hb;  off = 0;       }
    else if (i < 2097152) { src = (const float4*)p;  dst = g_pb;  off = 1048576; }
    else if (i < 2162688) { src = (const float4*)Wq; dst = g_Wqb; off = 2097152; }
    else if (i < 2228224) { src = (const float4*)Wk; dst = g_Wkb; off = 2162688; }
    else if (i < 2293760) { src = (const float4*)Wv; dst = g_Wvb; off = 2228224; }
    else                  { src = (const float4*)Wg; dst = g_Wgb; off = 2293760; }
    int j = i - off;
    *reinterpret_cast<uint2*>(dst + 4 * (size_t)j) = cvt4(src[j]);
}

// ---------------- GEMM mainloop (BM=BN=128, BK=32, 3-stage cp.async) ----------------
__device__ __forceinline__ void gemm_mainloop(
    const __nv_bfloat16* A0, const __nv_bfloat16* A1,
    const __nv_bfloat16* W, int K, int bm, int bn,
    unsigned sbase, int tid, int wrow, int wcol, int lane,
    float acc[4][4][4])
{
    const int KT = K / 32;
#pragma unroll
    for (int pre = 0; pre < 2; pre++) {
        const int k0 = pre * 32;
        const __nv_bfloat16* Ab = (A1 != nullptr && k0 >= CC) ? (A1 + (k0 - CC)) : (A0 + k0);
        const unsigned as = sbase + pre * 10240;
        const unsigned bs = sbase + 30720 + pre * 10240;
#pragma unroll
        for (int i = 0; i < 2; i++) {
            int slot = tid + i * 256;
            int row = slot >> 2, ch = slot & 3;
            cp16(as + row * 80 + ch * 16, Ab + (size_t)(bm + row) * CC + ch * 8);
            cp16(bs + row * 80 + ch * 16, W + (size_t)(bn + row) * K + k0 + ch * 8);
        }
        CP_COMMIT();
    }

    for (int kt = 0; kt < KT; kt++) {
        CP_WAIT1();
        __syncthreads();
        const unsigned as = sbase + (kt % 3) * 10240;
        const unsigned bs = sbase + 30720 + (kt % 3) * 10240;
#pragma unroll
        for (int ks = 0; ks < 2; ks++) {
            unsigned a[4][4], b[4][2], r[4];
#pragma unroll
            for (int mi = 0; mi < 4; mi++)
                ldsm4(a[mi], as + (unsigned)((wrow + mi * 16 + (lane & 15)) * 80
                                             + (2 * ks + (lane >> 4)) * 16));
#pragma unroll
            for (int pp = 0; pp < 2; pp++) {
                ldsm4(r, bs + (unsigned)((wcol + pp * 16 + (lane & 7) + ((lane >> 4) << 3)) * 80
                                         + (2 * ks + ((lane >> 3) & 1)) * 16));
                b[2*pp][0] = r[0]; b[2*pp][1] = r[1];
                b[2*pp+1][0] = r[2]; b[2*pp+1][1] = r[3];
            }
#pragma unroll
            for (int mi = 0; mi < 4; mi++)
#pragma unroll
                for (int ni = 0; ni < 4; ni++)
                    mma16816(acc[mi][ni], a[mi], b[ni]);
        }
        if (kt + 2 < KT) {
            const int k2 = kt + 2, k0 = k2 * 32;
            const __nv_bfloat16* Ab = (A1 != nullptr && k0 >= CC) ? (A1 + (k0 - CC)) : (A0 + k0);
            const unsigned as2 = sbase + (k2 % 3) * 10240;
            const unsigned bs2 = sbase + 30720 + (k2 % 3) * 10240;
#pragma unroll
            for (int i = 0; i < 2; i++) {
                int slot = tid + i * 256;
                int row = slot >> 2, ch = slot & 3;
                cp16(as2 + row * 80 + ch * 16, Ab + (size_t)(bm + row) * CC + ch * 8);
                cp16(bs2 + row * 80 + ch * 16, W + (size_t)(bn + row) * K + k0 + ch * 8);
            }
        }
        CP_COMMIT();
    }
    CP_WAIT0();
    __syncthreads();
}

// ---------------- projections: 3 GEMMs batched over blockIdx.z (chunk of rows) ----------------
__global__ void __launch_bounds__(256) gemm_proj(int bm_base)
{
    extern __shared__ char smem_p[];
    const unsigned sbase = smem_u32(smem_p);
    const int tid = threadIdx.x, warp = tid >> 5, lane = tid & 31;
    const int wrow = (warp >> 2) * 64, wcol = (warp & 3) * 32;
    const int bm = bm_base + blockIdx.y * 128, bn = blockIdx.x * 128;

    const __nv_bfloat16* A = (blockIdx.z == 0) ? g_hb : g_pb;
    const __nv_bfloat16* W = (blockIdx.z == 0) ? g_Wqb : ((blockIdx.z == 1) ? g_Wkb : g_Wvb);

    float acc[4][4][4];
#pragma unroll
    for (int i = 0; i < 4; i++)
#pragma unroll
        for (int j = 0; j < 4; j++)
#pragma unroll
            for (int k = 0; k < 4; k++) acc[i][j][k] = 0.f;

    gemm_mainloop(A, nullptr, W, CC, bm, bn, sbase, tid, wrow, wcol, lane, acc);

    const int g = lane >> 2, t = lane & 3;
    if (blockIdx.z == 2) {
#pragma unroll
        for (int mi = 0; mi < 4; mi++)
#pragma unroll
            for (int ni = 0; ni < 4; ni++) {
                int r0 = bm + wrow + mi * 16 + g;
                int c  = bn + wcol + ni * 8 + 2 * t;
                *reinterpret_cast<float2*>(&g_WV[(size_t)r0 * CC + c]) =
                    make_float2(acc[mi][ni][0], acc[mi][ni][1]);
                *reinterpret_cast<float2*>(&g_WV[(size_t)(r0 + 8) * CC + c]) =
                    make_float2(acc[mi][ni][2], acc[mi][ni][3]);
            }
    } else {
        __nv_bfloat16* outb = (blockIdx.z == 0) ? g_Qb : g_WKb;
#pragma unroll
        for (int mi = 0; mi < 4; mi++)
#pragma unroll
            for (int ni = 0; ni < 4; ni++) {
                int r0 = bm + wrow + mi * 16 + g;
                int c  = bn + wcol + ni * 8 + 2 * t;
                *reinterpret_cast<__nv_bfloat162*>(&outb[(size_t)r0 * CC + c]) =
                    __floats2bfloat162_rn(acc[mi][ni][0], acc[mi][ni][1]);
                *reinterpret_cast<__nv_bfloat162*>(&outb[(size_t)(r0 + 8) * CC + c]) =
                    __floats2bfloat162_rn(acc[mi][ni][2], acc[mi][ni][3]);
            }
    }
}

// ---------------- gate GEMM (K=2C) + fused surprise epilogue -> upd ----------------
__global__ void __launch_bounds__(256) gemm_gate(const float* __restrict__ bg, int bm_base)
{
    extern __shared__ char smem_g[];
    const unsigned sbase = smem_u32(smem_g);
    const int tid = threadIdx.x, warp = tid >> 5, lane = tid & 31;
    const int wrow = (warp >> 2) * 64, wcol = (warp & 3) * 32;
    const int bm = bm_base + blockIdx.y * 128, bn = blockIdx.x * 128;

    float acc[4][4][4];
#pragma unroll
    for (int i = 0; i < 4; i++)
#pragma unroll
        for (int j = 0; j < 4; j++)
#pragma unroll
            for (int k = 0; k < 4; k++) acc[i][j][k] = 0.f;

    gemm_mainloop(g_retrb, g_pb, g_Wgb, 2 * CC, bm, bn, sbase, tid, wrow, wcol, lane, acc);

    const int g = lane >> 2, t = lane & 3;
#pragma unroll
    for (int mi = 0; mi < 4; mi++)
#pragma unroll
        for (int ni = 0; ni < 4; ni++) {
            int cl = wcol + ni * 8 + 2 * t;
            int gc = bn + cl;
            float e0 = g_etas[gc], e1 = g_etas[gc + 1];
            float b0 = bg[gc],     b1 = bg[gc + 1];
#pragma unroll
            for (int hh = 0; hh < 2; hh++) {
                int r = bm + wrow + mi * 16 + g + hh * 8;
                size_t gi = (size_t)r * CC + gc;
                float2 wv2 = *reinterpret_cast<const float2*>(&g_WV[gi]);
                __nv_bfloat162 rb2 = *reinterpret_cast<const __nv_bfloat162*>(&g_retrb[gi]);
                float2 rt2 = __bfloat1622float2(rb2);
                float s0 = 1.f / (1.f + __expf(-(acc[mi][ni][hh*2+0] + b0)));
                float s1 = 1.f / (1.f + __expf(-(acc[mi][ni][hh*2+1] + b1)));
                *reinterpret_cast<float2*>(&g_upd[gi]) =
                    make_float2(e0 * s0 * (wv2.x - rt2.x), e1 * s1 * (wv2.y - rt2.y));
            }
        }
}

// ---------------- M update: M_new = M + ww_m * upd_c (one CTA per batch row) ----------------
__global__ void __launch_bounds__(256) mupd_kernel(
    const float* __restrict__ Mm, float* __restrict__ mnew, int b_base)
{
    const int b = b_base + blockIdx.x;
    __shared__ float us[CC];
    __shared__ float wws[NSLOT];
    const int tid = threadIdx.x;
    ((float2*)us)[tid] = ((const float2*)(g_upd + (size_t)b * CC))[tid];
    if (tid < NSLOT) wws[tid] = g_ww[(size_t)b * NSLOT + tid];
    __syncthreads();

    const float4* M4 = (const float4*)(Mm + (size_t)b * NSLOT * CC);
    float4* O4 = (float4*)(mnew + (size_t)b * NSLOT * CC);
#pragma unroll 4
    for (int idx = tid; idx < NSLOT * CC / 4; idx += 256) {
        const int m = idx >> 7, c4 = idx & 127;
        const float w = wws[m];
        float4 mv = __ldcs(M4 + idx);
        float4 u = ((const float4*)us)[c4];
        float4 o;
        o.x = mv.x + w * u.x;
        o.y = mv.y + w * u.y;
        o.z = mv.z + w * u.z;
        o.w = mv.w + w * u.w;
        __stcs(O4 + idx, o);
    }
}

// ---------------- fused attention / retrieval / Mk_new ----------------
__global__ void __launch_bounds__(256) attn_kernel(
    const float* __restrict__ h, const float* __restrict__ Mk,
    const float* __restrict__ Mm, float* __restrict__ out, int b_base)
{
    const int b = b_base + blockIdx.x;
    __shared__ float qs[CC], wks[CC];
    __shared__ float sm[NSLOT], tm[NSLOT], attnv[NSLOT], wws[NSLOT];

    const int tid = threadIdx.x;
    const int warp = tid >> 5, lane = tid & 31;
    const float* Mkb = Mk + (size_t)b * NSLOT * CC;
    const float* Mb  = Mm + (size_t)b * NSLOT * CC;

    {
        float2 q2 = __bfloat1622float2(((const __nv_bfloat162*)(g_Qb  + (size_t)b * CC))[tid]);
        float2 w2 = __bfloat1622float2(((const __nv_bfloat162*)(g_WKb + (size_t)b * CC))[tid]);
        qs [2*tid] = q2.x; qs [2*tid+1] = q2.y;
        wks[2*tid] = w2.x; wks[2*tid+1] = w2.y;
    }
    __syncthreads();

    // dual dot products vs M_keys rows (warp -> 4 slots)
#pragma unroll
    for (int mm = 0; mm < 4; mm++) {
        const int m = warp * 4 + mm;
        const float4* row4 = (const float4*)(Mkb + (size_t)m * CC);
        float s = 0.f, tt = 0.f;
#pragma unroll
        for (int it = 0; it < 4; it++) {
            float4 v = row4[lane + it * 32];
            float4 q = ((const float4*)qs)[lane + it * 32];
            float4 w = ((const float4*)wks)[lane + it * 32];
            s  += v.x*q.x + v.y*q.y + v.z*q.z + v.w*q.w;
            tt += v.x*w.x + v.y*w.y + v.z*w.z + v.w*w.w;
        }
#pragma unroll
        for (int o = 16; o > 0; o >>= 1) {
            s  += __shfl_xor_sync(0xffffffffu, s,  o);
            tt += __shfl_xor_sync(0xffffffffu, tt, o);
        }
        if (lane == 0) { sm[m] = s; tm[m] = tt; }
    }
    __syncthreads();

    if (tid < 32) {
        const float isq = 1.0f / sqrtf((float)CC);
        float s = sm[tid] * isq;
        float w = tm[tid] * isq;
        float mx = s;
#pragma unroll
        for (int o = 16; o > 0; o >>= 1) mx = fmaxf(mx, __shfl_xor_sync(0xffffffffu, mx, o));
        float e = expf(s - mx), sum = e;
#pragma unroll
        for (int o = 16; o > 0; o >>= 1) sum += __shfl_xor_sync(0xffffffffu, sum, o);
        attnv[tid] = e / sum;

        float mx2 = w;
#pragma unroll
        for (int o = 16; o > 0; o >>= 1) mx2 = fmaxf(mx2, __shfl_xor_sync(0xffffffffu, mx2, o));
        float e2 = expf(w - mx2), sum2 = e2;
#pragma unroll
        for (int o = 16; o > 0; o >>= 1) sum2 += __shfl_xor_sync(0xffffffffu, sum2, o);
        const float wv = e2 / sum2;
        wws[tid] = wv;
        g_ww[(size_t)b * NSLOT + tid] = wv;
    }
    __syncthreads();

    // Mk_new FIRST (Mk hot in L2 from the dot-product phase)
    {
        float* mkout = out + (size_t)BB * CC + (size_t)BB * NSLOT * CC + (size_t)b * NSLOT * CC;
        const float4* Mk4 = (const float4*)Mkb;
        float4* mo4 = (float4*)mkout;
        for (int idx = tid; idx < NSLOT * CC / 4; idx += 256) {
            const int m = idx >> 7;
            const int c4 = idx & 127;
            float4 mk = Mk4[idx];
            float4 wk = ((const float4*)wks)[c4];
            float w = wws[m] * 0.01f;
            float4 o;
            o.x = mk.x + w * (wk.x - mk.x);
            o.y = mk.y + w * (wk.y - mk.y);
            o.z = mk.z + w * (wk.z - mk.z);
            o.w = mk.w + w * (wk.w - mk.w);
            __stcs(mo4 + idx, o);
        }
    }

    // retrieval (streams M, evict-first) + out + bf16 retr for gate GEMM
    {
        const float2* M2 = (const float2*)Mb;
        float2 r = make_float2(0.f, 0.f);
#pragma unroll
        for (int m = 0; m < NSLOT; m++) {
            float2 v = __ldcs(M2 + m * (CC / 2) + tid);
            r.x += attnv[m] * v.x;
            r.y += attnv[m] * v.y;
        }
        const float2* h2 = (const float2*)(h + (size_t)b * CC);
        float2 hv = h2[tid];
        __stcs((float2*)(out + (size_t)b * CC) + tid, make_float2(hv.x + r.x, hv.y + r.y));
        __nv_bfloat162 rb = __floats2bfloat162_rn(r.x, r.y);
        ((__nv_bfloat162*)(g_retrb + (size_t)b * CC))[tid] = rb;
    }
}

// ---------------- launch: 2-stream software pipeline over 4 batch chunks ----------------
extern "C" void kernel_launch(void* const* d_in, const int* in_sizes, int n_in,
                              void* d_out, int out_size)
{
    const float* h   = (const float*)d_in[0];
    const float* p   = (const float*)d_in[1];
    const float* M   = (const float*)d_in[2];
    const float* Mk  = (const float*)d_in[3];
    const float* Wq  = (const float*)d_in[4];
    const float* Wk  = (const float*)d_in[5];
    const float* Wv  = (const float*)d_in[6];
    const float* Wg  = (const float*)d_in[7];
    const float* bg  = (const float*)d_in[8];
    const float* eta = (const float*)d_in[9];
    float* out = (float*)d_out;

    static cudaStream_t s1 = nullptr;
    static cudaEvent_t evA[NCH], evB;
    if (s1 == nullptr) {
        cudaFuncSetAttribute(gemm_proj, cudaFuncAttributeMaxDynamicSharedMemorySize, 61440);
        cudaFuncSetAttribute(gemm_gate, cudaFuncAttributeMaxDynamicSharedMemorySize, 61440);
        cudaStreamCreateWithFlags(&s1, cudaStreamNonBlocking);
        for (int i = 0; i < NCH; i++)
            cudaEventCreateWithFlags(&evA[i], cudaEventDisableTiming);
        cudaEventCreateWithFlags(&evB, cudaEventDisableTiming);
    }

    // front: bf16 conversion (+ eta sigmoid) on the main stream
    convert_kernel<<<9472, 256>>>(h, p, Wq, Wk, Wv, Wg, eta);

    for (int c = 0; c < NCH; c++) {
        const int base = c * RCH;
        // stream 0: projections for this chunk, then attention/retrieval/Mk_new
        gemm_proj<<<dim3(4, RCH / 128, 3), 256, 61440>>>(base);
        attn_kernel<<<RCH, 256>>>(h, Mk, M, out, base);
        cudaEventRecord(evA[c], 0);
        // stream 1: gate GEMM + M_new streaming for this chunk, overlapped with next attn
        cudaStreamWaitEvent(s1, evA[c], 0);
        gemm_gate<<<dim3(4, RCH / 128), 256, 61440, s1>>>(bg, base);
        mupd_kernel<<<RCH, 256, 0, s1>>>(M, out + (size_t)BB * CC, base);
    }

    // join stream 1 back into the main stream
    cudaEventRecord(evB, s1);
    cudaStreamWaitEvent(0, evB, 0);
}

// round 8
// speedup vs baseline: 1.0208x; 1.0208x over previous
#include <cuda_runtime.h>
#include <cuda_bf16.h>
#include <math.h>

#define BB 8192
#define CC 512
#define NSLOT 32
#define HB 4096   // rows per half

// ---------------- scratch (no allocations allowed) ----------------
__device__ float g_upd [BB*CC];
__device__ float g_ww  [BB*NSLOT];
__device__ float g_etas[CC];
__device__ __nv_bfloat16 g_Qb   [BB*CC];
__device__ __nv_bfloat16 g_WKb  [BB*CC];
__device__ __nv_bfloat16 g_WVb  [BB*CC];
__device__ __nv_bfloat16 g_hb   [BB*CC];
__device__ __nv_bfloat16 g_pb   [BB*CC];
__device__ __nv_bfloat16 g_retrb[BB*CC];
__device__ __nv_bfloat16 g_Wqb  [CC*CC];
__device__ __nv_bfloat16 g_Wkb  [CC*CC];
__device__ __nv_bfloat16 g_Wvb  [CC*CC];
__device__ __nv_bfloat16 g_Wgb  [2*CC*CC];

// ---------------- helpers ----------------
__device__ __forceinline__ uint2 cvt4(float4 v) {
    __nv_bfloat162 lo = __floats2bfloat162_rn(v.x, v.y);
    __nv_bfloat162 hi = __floats2bfloat162_rn(v.z, v.w);
    uint2 r;
    r.x = *reinterpret_cast<unsigned int*>(&lo);
    r.y = *reinterpret_cast<unsigned int*>(&hi);
    return r;
}

__device__ __forceinline__ unsigned smem_u32(const void* p) {
    unsigned a;
    asm volatile("{ .reg .u64 t; cvta.to.shared.u64 t, %1; cvt.u32.u64 %0, t; }"
                 : "=r"(a) : "l"(p));
    return a;
}

__device__ __forceinline__ void cp16(unsigned dst, const void* src) {
    asm volatile("cp.async.cg.shared.global [%0], [%1], 16;" :: "r"(dst), "l"(src));
}
#define CP_COMMIT() asm volatile("cp.async.commit_group;" ::)
#define CP_WAIT1()  asm volatile("cp.async.wait_group 1;" ::)
#define CP_WAIT0()  asm volatile("cp.async.wait_group 0;" ::)

__device__ __forceinline__ void ldsm4(unsigned* r, unsigned a) {
    asm volatile("ldmatrix.sync.aligned.m8n8.x4.shared.b16 {%0,%1,%2,%3}, [%4];"
                 : "=r"(r[0]), "=r"(r[1]), "=r"(r[2]), "=r"(r[3]) : "r"(a));
}

__device__ __forceinline__ void mma16816(float* d, const unsigned* a, const unsigned* b) {
    asm volatile(
        "mma.sync.aligned.m16n8k16.row.col.f32.bf16.bf16.f32 "
        "{%0,%1,%2,%3}, {%4,%5,%6,%7}, {%8,%9}, {%0,%1,%2,%3};\n"
        : "+f"(d[0]), "+f"(d[1]), "+f"(d[2]), "+f"(d[3])
        : "r"(a[0]), "r"(a[1]), "r"(a[2]), "r"(a[3]), "r"(b[0]), "r"(b[1]));
}

// ---------------- one-shot bf16 conversion ----------------
__global__ void __launch_bounds__(256) convert_kernel(
    const float* __restrict__ h, const float* __restrict__ p,
    const float* __restrict__ Wq, const float* __restrict__ Wk,
    const float* __restrict__ Wv, const float* __restrict__ Wg,
    const float* __restrict__ eta)
{
    if (blockIdx.x == 0 && threadIdx.x < 256) {
        for (int c = threadIdx.x; c < CC; c += 256)
            g_etas[c] = 1.f / (1.f + __expf(-eta[c]));
    }
    int i = blockIdx.x * 256 + threadIdx.x;
    const float4* src; __nv_bfloat16* dst; int off;
    if      (i < 1048576) { src = (const float4*)h;  dst = g_hb;  off = 0;       }
    else if (i < 2097152) { src = (const float4*)p;  dst = g_pb;  off = 1048576; }
    else if (i < 2162688) { src = (const float4*)Wq; dst = g_Wqb; off = 2097152; }
    else if (i < 2228224) { src = (const float4*)Wk; dst = g_Wkb; off = 2162688; }
    else if (i < 2293760) { src = (const float4*)Wv; dst = g_Wvb; off = 2228224; }
    else                  { src = (const float4*)Wg; dst = g_Wgb; off = 2293760; }
    int j = i - off;
    *reinterpret_cast<uint2*>(dst + 4 * (size_t)j) = cvt4(src[j]);
}

// ---------------- GEMM mainloop (BM=BN=128, BK=32, 3-stage cp.async) ----------------
__device__ __forceinline__ void gemm_mainloop(
    const __nv_bfloat16* A0, const __nv_bfloat16* A1,
    const __nv_bfloat16* W, int K, int bm, int bn,
    unsigned sbase, int tid, int wrow, int wcol, int lane,
    float acc[4][4][4])
{
    const int KT = K / 32;
#pragma unroll
    for (int pre = 0; pre < 2; pre++) {
        const int k0 = pre * 32;
        const __nv_bfloat16* Ab = (A1 != nullptr && k0 >= CC) ? (A1 + (k0 - CC)) : (A0 + k0);
        const unsigned as = sbase + pre * 10240;
        const unsigned bs = sbase + 30720 + pre * 10240;
#pragma unroll
        for (int i = 0; i < 2; i++) {
            int slot = tid + i * 256;
            int row = slot >> 2, ch = slot & 3;
            cp16(as + row * 80 + ch * 16, Ab + (size_t)(bm + row) * CC + ch * 8);
            cp16(bs + row * 80 + ch * 16, W + (size_t)(bn + row) * K + k0 + ch * 8);
        }
        CP_COMMIT();
    }

    for (int kt = 0; kt < KT; kt++) {
        CP_WAIT1();
        __syncthreads();
        const unsigned as = sbase + (kt % 3) * 10240;
        const unsigned bs = sbase + 30720 + (kt % 3) * 10240;
#pragma unroll
        for (int ks = 0; ks < 2; ks++) {
            unsigned a[4][4], b[4][2], r[4];
#pragma unroll
            for (int mi = 0; mi < 4; mi++)
                ldsm4(a[mi], as + (unsigned)((wrow + mi * 16 + (lane & 15)) * 80
                                             + (2 * ks + (lane >> 4)) * 16));
#pragma unroll
            for (int pp = 0; pp < 2; pp++) {
                ldsm4(r, bs + (unsigned)((wcol + pp * 16 + (lane & 7) + ((lane >> 4) << 3)) * 80
                                         + (2 * ks + ((lane >> 3) & 1)) * 16));
                b[2*pp][0] = r[0]; b[2*pp][1] = r[1];
                b[2*pp+1][0] = r[2]; b[2*pp+1][1] = r[3];
            }
#pragma unroll
            for (int mi = 0; mi < 4; mi++)
#pragma unroll
                for (int ni = 0; ni < 4; ni++)
                    mma16816(acc[mi][ni], a[mi], b[ni]);
        }
        if (kt + 2 < KT) {
            const int k2 = kt + 2, k0 = k2 * 32;
            const __nv_bfloat16* Ab = (A1 != nullptr && k0 >= CC) ? (A1 + (k0 - CC)) : (A0 + k0);
            const unsigned as2 = sbase + (k2 % 3) * 10240;
            const unsigned bs2 = sbase + 30720 + (k2 % 3) * 10240;
#pragma unroll
            for (int i = 0; i < 2; i++) {
                int slot = tid + i * 256;
                int row = slot >> 2, ch = slot & 3;
                cp16(as2 + row * 80 + ch * 16, Ab + (size_t)(bm + row) * CC + ch * 8);
                cp16(bs2 + row * 80 + ch * 16, W + (size_t)(bn + row) * K + k0 + ch * 8);
            }
        }
        CP_COMMIT();
    }
    CP_WAIT0();
    __syncthreads();
}

// ---------------- projections: 3 GEMMs batched over blockIdx.z (half of rows) ----------------
__global__ void __launch_bounds__(256) gemm_proj(int bm_base)
{
    extern __shared__ char smem_p[];
    const unsigned sbase = smem_u32(smem_p);
    const int tid = threadIdx.x, warp = tid >> 5, lane = tid & 31;
    const int wrow = (warp >> 2) * 64, wcol = (warp & 3) * 32;
    const int bm = bm_base + blockIdx.y * 128, bn = blockIdx.x * 128;

    const __nv_bfloat16* A = (blockIdx.z == 0) ? g_hb : g_pb;
    const __nv_bfloat16* W = (blockIdx.z == 0) ? g_Wqb : ((blockIdx.z == 1) ? g_Wkb : g_Wvb);
    __nv_bfloat16* outb = (blockIdx.z == 0) ? g_Qb : ((blockIdx.z == 1) ? g_WKb : g_WVb);

    float acc[4][4][4];
#pragma unroll
    for (int i = 0; i < 4; i++)
#pragma unroll
        for (int j = 0; j < 4; j++)
#pragma unroll
            for (int k = 0; k < 4; k++) acc[i][j][k] = 0.f;

    gemm_mainloop(A, nullptr, W, CC, bm, bn, sbase, tid, wrow, wcol, lane, acc);

    const int g = lane >> 2, t = lane & 3;
#pragma unroll
    for (int mi = 0; mi < 4; mi++)
#pragma unroll
        for (int ni = 0; ni < 4; ni++) {
            int r0 = bm + wrow + mi * 16 + g;
            int c  = bn + wcol + ni * 8 + 2 * t;
            *reinterpret_cast<__nv_bfloat162*>(&outb[(size_t)r0 * CC + c]) =
                __floats2bfloat162_rn(acc[mi][ni][0], acc[mi][ni][1]);
            *reinterpret_cast<__nv_bfloat162*>(&outb[(size_t)(r0 + 8) * CC + c]) =
                __floats2bfloat162_rn(acc[mi][ni][2], acc[mi][ni][3]);
        }
}

// ---------------- gate GEMM (K=2C) + fused surprise epilogue -> upd ----------------
__global__ void __launch_bounds__(256) gemm_gate(const float* __restrict__ bg, int bm_base)
{
    extern __shared__ char smem_g[];
    const unsigned sbase = smem_u32(smem_g);
    const int tid = threadIdx.x, warp = tid >> 5, lane = tid & 31;
    const int wrow = (warp >> 2) * 64, wcol = (warp & 3) * 32;
    const int bm = bm_base + blockIdx.y * 128, bn = blockIdx.x * 128;

    float acc[4][4][4];
#pragma unroll
    for (int i = 0; i < 4; i++)
#pragma unroll
        for (int j = 0; j < 4; j++)
#pragma unroll
            for (int k = 0; k < 4; k++) acc[i][j][k] = 0.f;

    gemm_mainloop(g_retrb, g_pb, g_Wgb, 2 * CC, bm, bn, sbase, tid, wrow, wcol, lane, acc);

    const int g = lane >> 2, t = lane & 3;
#pragma unroll
    for (int mi = 0; mi < 4; mi++)
#pragma unroll
        for (int ni = 0; ni < 4; ni++) {
            int cl = wcol + ni * 8 + 2 * t;
            int gc = bn + cl;
            float e0 = g_etas[gc], e1 = g_etas[gc + 1];
            float b0 = bg[gc],     b1 = bg[gc + 1];
#pragma unroll
            for (int hh = 0; hh < 2; hh++) {
                int r = bm + wrow + mi * 16 + g + hh * 8;
                size_t gi = (size_t)r * CC + gc;
                float2 wv2 = __bfloat1622float2(
                    *reinterpret_cast<const __nv_bfloat162*>(&g_WVb[gi]));
                float2 rt2 = __bfloat1622float2(
                    *reinterpret_cast<const __nv_bfloat162*>(&g_retrb[gi]));
                float s0 = 1.f / (1.f + __expf(-(acc[mi][ni][hh*2+0] + b0)));
                float s1 = 1.f / (1.f + __expf(-(acc[mi][ni][hh*2+1] + b1)));
                *reinterpret_cast<float2*>(&g_upd[gi]) =
                    make_float2(e0 * s0 * (wv2.x - rt2.x), e1 * s1 * (wv2.y - rt2.y));
            }
        }
}

// ---------------- M update: M_new = M + ww_m * upd_c (one CTA per batch row) ----------------
__global__ void __launch_bounds__(256) mupd_kernel(
    const float* __restrict__ Mm, float* __restrict__ mnew, int b_base)
{
    const int b = b_base + blockIdx.x;
    __shared__ float us[CC];
    __shared__ float wws[NSLOT];
    const int tid = threadIdx.x;
    ((float2*)us)[tid] = ((const float2*)(g_upd + (size_t)b * CC))[tid];
    if (tid < NSLOT) wws[tid] = g_ww[(size_t)b * NSLOT + tid];
    __syncthreads();

    const float4* M4 = (const float4*)(Mm + (size_t)b * NSLOT * CC);
    float4* O4 = (float4*)(mnew + (size_t)b * NSLOT * CC);
#pragma unroll 4
    for (int idx = tid; idx < NSLOT * CC / 4; idx += 256) {
        const int m = idx >> 7, c4 = idx & 127;
        const float w = wws[m];
        float4 mv = __ldcs(M4 + idx);
        float4 u = ((const float4*)us)[c4];
        float4 o;
        o.x = mv.x + w * u.x;
        o.y = mv.y + w * u.y;
        o.z = mv.z + w * u.z;
        o.w = mv.w + w * u.w;
        __stcs(O4 + idx, o);
    }
}

// ---------------- fused attention / retrieval / Mk_new ----------------
__global__ void __launch_bounds__(256) attn_kernel(
    const float* __restrict__ h, const float* __restrict__ Mk,
    const float* __restrict__ Mm, float* __restrict__ out, int b_base)
{
    const int b = b_base + blockIdx.x;
    __shared__ float qs[CC], wks[CC];
    __shared__ float sm[NSLOT], tm[NSLOT], attnv[NSLOT], wws[NSLOT];

    const int tid = threadIdx.x;
    const int warp = tid >> 5, lane = tid & 31;
    const float* Mkb = Mk + (size_t)b * NSLOT * CC;
    const float* Mb  = Mm + (size_t)b * NSLOT * CC;

    {
        float2 q2 = __bfloat1622float2(((const __nv_bfloat162*)(g_Qb  + (size_t)b * CC))[tid]);
        float2 w2 = __bfloat1622float2(((const __nv_bfloat162*)(g_WKb + (size_t)b * CC))[tid]);
        qs [2*tid] = q2.x; qs [2*tid+1] = q2.y;
        wks[2*tid] = w2.x; wks[2*tid+1] = w2.y;
    }
    __syncthreads();

    // dual dot products vs M_keys rows (warp -> 4 slots)
#pragma unroll
    for (int mm = 0; mm < 4; mm++) {
        const int m = warp * 4 + mm;
        const float4* row4 = (const float4*)(Mkb + (size_t)m * CC);
        float s = 0.f, tt = 0.f;
#pragma unroll
        for (int it = 0; it < 4; it++) {
            float4 v = row4[lane + it * 32];
            float4 q = ((const float4*)qs)[lane + it * 32];
            float4 w = ((const float4*)wks)[lane + it * 32];
            s  += v.x*q.x + v.y*q.y + v.z*q.z + v.w*q.w;
            tt += v.x*w.x + v.y*w.y + v.z*w.z + v.w*w.w;
        }
#pragma unroll
        for (int o = 16; o > 0; o >>= 1) {
            s  += __shfl_xor_sync(0xffffffffu, s,  o);
            tt += __shfl_xor_sync(0xffffffffu, tt, o);
        }
        if (lane == 0) { sm[m] = s; tm[m] = tt; }
    }
    __syncthreads();

    if (tid < 32) {
        const float isq = 1.0f / sqrtf((float)CC);
        float s = sm[tid] * isq;
        float w = tm[tid] * isq;
        float mx = s;
#pragma unroll
        for (int o = 16; o > 0; o >>= 1) mx = fmaxf(mx, __shfl_xor_sync(0xffffffffu, mx, o));
        float e = expf(s - mx), sum = e;
#pragma unroll
        for (int o = 16; o > 0; o >>= 1) sum += __shfl_xor_sync(0xffffffffu, sum, o);
        attnv[tid] = e / sum;

        float mx2 = w;
#pragma unroll
        for (int o = 16; o > 0; o >>= 1) mx2 = fmaxf(mx2, __shfl_xor_sync(0xffffffffu, mx2, o));
        float e2 = expf(w - mx2), sum2 = e2;
#pragma unroll
        for (int o = 16; o > 0; o >>= 1) sum2 += __shfl_xor_sync(0xffffffffu, sum2, o);
        const float wv = e2 / sum2;
        wws[tid] = wv;
        g_ww[(size_t)b * NSLOT + tid] = wv;
    }
    __syncthreads();

    // Mk_new FIRST (Mk hot in L2 from the dot-product phase)
    {
        float* mkout = out + (size_t)BB * CC + (size_t)BB * NSLOT * CC + (size_t)b * NSLOT * CC;
        const float4* Mk4 = (const float4*)Mkb;
        float4* mo4 = (float4*)mkout;
        for (int idx = tid; idx < NSLOT * CC / 4; idx += 256) {
            const int m = idx >> 7;
            const int c4 = idx & 127;
            float4 mk = Mk4[idx];
            float4 wk = ((const float4*)wks)[c4];
            float w = wws[m] * 0.01f;
            float4 o;
            o.x = mk.x + w * (wk.x - mk.x);
            o.y = mk.y + w * (wk.y - mk.y);
            o.z = mk.z + w * (wk.z - mk.z);
            o.w = mk.w + w * (wk.w - mk.w);
            __stcs(mo4 + idx, o);
        }
    }

    // retrieval (streams M, evict-first) + out + bf16 retr for gate GEMM
    {
        const float2* M2 = (const float2*)Mb;
        float2 r = make_float2(0.f, 0.f);
#pragma unroll
        for (int m = 0; m < NSLOT; m++) {
            float2 v = __ldcs(M2 + m * (CC / 2) + tid);
            r.x += attnv[m] * v.x;
            r.y += attnv[m] * v.y;
        }
        const float2* h2 = (const float2*)(h + (size_t)b * CC);
        float2 hv = h2[tid];
        __stcs((float2*)(out + (size_t)b * CC) + tid, make_float2(hv.x + r.x, hv.y + r.y));
        __nv_bfloat162 rb = __floats2bfloat162_rn(r.x, r.y);
        ((__nv_bfloat162*)(g_retrb + (size_t)b * CC))[tid] = rb;
    }
}

// ---------------- launch: 2-half pipeline; tensor kernels never below 128 CTAs ----------------
extern "C" void kernel_launch(void* const* d_in, const int* in_sizes, int n_in,
                              void* d_out, int out_size)
{
    const float* h   = (const float*)d_in[0];
    const float* p   = (const float*)d_in[1];
    const float* M   = (const float*)d_in[2];
    const float* Mk  = (const float*)d_in[3];
    const float* Wq  = (const float*)d_in[4];
    const float* Wk  = (const float*)d_in[5];
    const float* Wv  = (const float*)d_in[6];
    const float* Wg  = (const float*)d_in[7];
    const float* bg  = (const float*)d_in[8];
    const float* eta = (const float*)d_in[9];
    float* out = (float*)d_out;
    float* mnew = out + (size_t)BB * CC;

    static cudaStream_t s1 = nullptr;
    static cudaEvent_t evC, evP1, evA0, evA1, evE;
    if (s1 == nullptr) {
        cudaFuncSetAttribute(gemm_proj, cudaFuncAttributeMaxDynamicSharedMemorySize, 61440);
        cudaFuncSetAttribute(gemm_gate, cudaFuncAttributeMaxDynamicSharedMemorySize, 61440);
        cudaStreamCreateWithFlags(&s1, cudaStreamNonBlocking);
        cudaEventCreateWithFlags(&evC,  cudaEventDisableTiming);
        cudaEventCreateWithFlags(&evP1, cudaEventDisableTiming);
        cudaEventCreateWithFlags(&evA0, cudaEventDisableTiming);
        cudaEventCreateWithFlags(&evA1, cudaEventDisableTiming);
        cudaEventCreateWithFlags(&evE,  cudaEventDisableTiming);
    }

    // front: bf16 conversion (+ eta sigmoid)
    convert_kernel<<<9472, 256>>>(h, p, Wq, Wk, Wv, Wg, eta);
    cudaEventRecord(evC, 0);

    // projections: half A on s0, half B on s1 (each 384 CTAs)
    gemm_proj<<<dim3(4, HB / 128, 3), 256, 61440>>>(0);
    cudaStreamWaitEvent(s1, evC, 0);
    gemm_proj<<<dim3(4, HB / 128, 3), 256, 61440, s1>>>(HB);
    cudaEventRecord(evP1, s1);

    // attention half A, then half B (s0)
    attn_kernel<<<HB, 256>>>(h, Mk, M, out, 0);
    cudaEventRecord(evA0, 0);
    cudaStreamWaitEvent(0, evP1, 0);
    attn_kernel<<<HB, 256>>>(h, Mk, M, out, HB);
    cudaEventRecord(evA1, 0);

    // s1: gate+mupd half A overlap attn half B; then half B as tail
    cudaStreamWaitEvent(s1, evA0, 0);
    gemm_gate<<<dim3(4, HB / 128), 256, 61440, s1>>>(bg, 0);
    mupd_kernel<<<HB, 256, 0, s1>>>(M, mnew, 0);
    cudaStreamWaitEvent(s1, evA1, 0);
    gemm_gate<<<dim3(4, HB / 128), 256, 61440, s1>>>(bg, HB);
    mupd_kernel<<<HB, 256, 0, s1>>>(M, mnew, HB);

    cudaEventRecord(evE, s1);
    cudaStreamWaitEvent(0, evE, 0);
}

// round 13
// speedup vs baseline: 1.0630x; 1.0413x over previous
#include <cuda_runtime.h>
#include <cuda_bf16.h>
#include <math.h>

#define BB 8192
#define CC 512
#define NSLOT 32
#define HB 4096   // rows per half

// ---------------- scratch (no allocations allowed) ----------------
__device__ float g_upd [BB*CC];
__device__ float g_ww  [BB*NSLOT];
__device__ float g_etas[CC];
__device__ __nv_bfloat16 g_Qb   [BB*CC];
__device__ __nv_bfloat16 g_WKb  [BB*CC];
__device__ __nv_bfloat16 g_WVb  [BB*CC];
__device__ __nv_bfloat16 g_hb   [BB*CC];
__device__ __nv_bfloat16 g_pb   [BB*CC];
__device__ __nv_bfloat16 g_retrb[BB*CC];
__device__ __nv_bfloat16 g_Wqb  [CC*CC];
__device__ __nv_bfloat16 g_Wkb  [CC*CC];
__device__ __nv_bfloat16 g_Wvb  [CC*CC];
__device__ __nv_bfloat16 g_Wgb  [2*CC*CC];

// ---------------- helpers ----------------
__device__ __forceinline__ uint2 cvt4(float4 v) {
    __nv_bfloat162 lo = __floats2bfloat162_rn(v.x, v.y);
    __nv_bfloat162 hi = __floats2bfloat162_rn(v.z, v.w);
    uint2 r;
    r.x = *reinterpret_cast<unsigned int*>(&lo);
    r.y = *reinterpret_cast<unsigned int*>(&hi);
    return r;
}

__device__ __forceinline__ unsigned smem_u32(const void* p) {
    unsigned a;
    asm volatile("{ .reg .u64 t; cvta.to.shared.u64 t, %1; cvt.u32.u64 %0, t; }"
                 : "=r"(a) : "l"(p));
    return a;
}

__device__ __forceinline__ void cp16(unsigned dst, const void* src) {
    asm volatile("cp.async.cg.shared.global [%0], [%1], 16;" :: "r"(dst), "l"(src));
}
#define CP_COMMIT() asm volatile("cp.async.commit_group;" ::)
#define CP_WAIT1()  asm volatile("cp.async.wait_group 1;" ::)
#define CP_WAIT0()  asm volatile("cp.async.wait_group 0;" ::)

__device__ __forceinline__ void ldsm4(unsigned* r, unsigned a) {
    asm volatile("ldmatrix.sync.aligned.m8n8.x4.shared.b16 {%0,%1,%2,%3}, [%4];"
                 : "=r"(r[0]), "=r"(r[1]), "=r"(r[2]), "=r"(r[3]) : "r"(a));
}

__device__ __forceinline__ void mma16816(float* d, const unsigned* a, const unsigned* b) {
    asm volatile(
        "mma.sync.aligned.m16n8k16.row.col.f32.bf16.bf16.f32 "
        "{%0,%1,%2,%3}, {%4,%5,%6,%7}, {%8,%9}, {%0,%1,%2,%3};\n"
        : "+f"(d[0]), "+f"(d[1]), "+f"(d[2]), "+f"(d[3])
        : "r"(a[0]), "r"(a[1]), "r"(a[2]), "r"(a[3]), "r"(b[0]), "r"(b[1]));
}

// ---------------- one-shot bf16 conversion ----------------
__global__ void __launch_bounds__(256) convert_kernel(
    const float* __restrict__ h, const float* __restrict__ p,
    const float* __restrict__ Wq, const float* __restrict__ Wk,
    const float* __restrict__ Wv, const float* __restrict__ Wg,
    const float* __restrict__ eta)
{
    if (blockIdx.x == 0 && threadIdx.x < 256) {
        for (int c = threadIdx.x; c < CC; c += 256)
            g_etas[c] = 1.f / (1.f + __expf(-eta[c]));
    }
    int i = blockIdx.x * 256 + threadIdx.x;
    const float4* src; __nv_bfloat16* dst; int off;
    if      (i < 1048576) { src = (const float4*)h;  dst = g_hb;  off = 0;       }
    else if (i < 2097152) { src = (const float4*)p;  dst = g_pb;  off = 1048576; }
    else if (i < 2162688) { src = (const float4*)Wq; dst = g_Wqb; off = 2097152; }
    else if (i < 2228224) { src = (const float4*)Wk; dst = g_Wkb; off = 2162688; }
    else if (i < 2293760) { src = (const float4*)Wv; dst = g_Wvb; off = 2228224; }
    else                  { src = (const float4*)Wg; dst = g_Wgb; off = 2293760; }
    int j = i - off;
    *reinterpret_cast<uint2*>(dst + 4 * (size_t)j) = cvt4(src[j]);
}

// ---------------- GEMM mainloop (BM=BN=128, BK=32, 3-stage cp.async) ----------------
__device__ __forceinline__ void gemm_mainloop(
    const __nv_bfloat16* A0, const __nv_bfloat16* A1,
    const __nv_bfloat16* W, int K, int bm, int bn,
    unsigned sbase, int tid, int wrow, int wcol, int lane,
    float acc[4][4][4])
{
    const int KT = K / 32;
#pragma unroll
    for (int pre = 0; pre < 2; pre++) {
        const int k0 = pre * 32;
        const __nv_bfloat16* Ab = (A1 != nullptr && k0 >= CC) ? (A1 + (k0 - CC)) : (A0 + k0);
        const unsigned as = sbase + pre * 10240;
        const unsigned bs = sbase + 30720 + pre * 10240;
#pragma unroll
        for (int i = 0; i < 2; i++) {
            int slot = tid + i * 256;
            int row = slot >> 2, ch = slot & 3;
            cp16(as + row * 80 + ch * 16, Ab + (size_t)(bm + row) * CC + ch * 8);
            cp16(bs + row * 80 + ch * 16, W + (size_t)(bn + row) * K + k0 + ch * 8);
        }
        CP_COMMIT();
    }

    for (int kt = 0; kt < KT; kt++) {
        CP_WAIT1();
        __syncthreads();
        const unsigned as = sbase + (kt % 3) * 10240;
        const unsigned bs = sbase + 30720 + (kt % 3) * 10240;
#pragma unroll
        for (int ks = 0; ks < 2; ks++) {
            unsigned a[4][4], b[4][2], r[4];
#pragma unroll
            for (int mi = 0; mi < 4; mi++)
                ldsm4(a[mi], as + (unsigned)((wrow + mi * 16 + (lane & 15)) * 80
                                             + (2 * ks + (lane >> 4)) * 16));
#pragma unroll
            for (int pp = 0; pp < 2; pp++) {
                ldsm4(r, bs + (unsigned)((wcol + pp * 16 + (lane & 7) + ((lane >> 4) << 3)) * 80
                                         + (2 * ks + ((lane >> 3) & 1)) * 16));
                b[2*pp][0] = r[0]; b[2*pp][1] = r[1];
                b[2*pp+1][0] = r[2]; b[2*pp+1][1] = r[3];
            }
#pragma unroll
            for (int mi = 0; mi < 4; mi++)
#pragma unroll
                for (int ni = 0; ni < 4; ni++)
                    mma16816(acc[mi][ni], a[mi], b[ni]);
        }
        if (kt + 2 < KT) {
            const int k2 = kt + 2, k0 = k2 * 32;
            const __nv_bfloat16* Ab = (A1 != nullptr && k0 >= CC) ? (A1 + (k0 - CC)) : (A0 + k0);
            const unsigned as2 = sbase + (k2 % 3) * 10240;
            const unsigned bs2 = sbase + 30720 + (k2 % 3) * 10240;
#pragma unroll
            for (int i = 0; i < 2; i++) {
                int slot = tid + i * 256;
                int row = slot >> 2, ch = slot & 3;
                cp16(as2 + row * 80 + ch * 16, Ab + (size_t)(bm + row) * CC + ch * 8);
                cp16(bs2 + row * 80 + ch * 16, W + (size_t)(bn + row) * K + k0 + ch * 8);
            }
        }
        CP_COMMIT();
    }
    CP_WAIT0();
    __syncthreads();
}

// ---------------- projections: GEMMs batched over blockIdx.z + zoff ----------------
__global__ void __launch_bounds__(256) gemm_proj(int zoff)
{
    extern __shared__ char smem_p[];
    const unsigned sbase = smem_u32(smem_p);
    const int tid = threadIdx.x, warp = tid >> 5, lane = tid & 31;
    const int wrow = (warp >> 2) * 64, wcol = (warp & 3) * 32;
    const int bm = blockIdx.y * 128, bn = blockIdx.x * 128;
    const int z = blockIdx.z + zoff;

    const __nv_bfloat16* A = (z == 0) ? g_hb : g_pb;
    const __nv_bfloat16* W = (z == 0) ? g_Wqb : ((z == 1) ? g_Wkb : g_Wvb);
    __nv_bfloat16* outb = (z == 0) ? g_Qb : ((z == 1) ? g_WKb : g_WVb);

    float acc[4][4][4];
#pragma unroll
    for (int i = 0; i < 4; i++)
#pragma unroll
        for (int j = 0; j < 4; j++)
#pragma unroll
            for (int k = 0; k < 4; k++) acc[i][j][k] = 0.f;

    gemm_mainloop(A, nullptr, W, CC, bm, bn, sbase, tid, wrow, wcol, lane, acc);

    const int g = lane >> 2, t = lane & 3;
#pragma unroll
    for (int mi = 0; mi < 4; mi++)
#pragma unroll
        for (int ni = 0; ni < 4; ni++) {
            int r0 = bm + wrow + mi * 16 + g;
            int c  = bn + wcol + ni * 8 + 2 * t;
            *reinterpret_cast<__nv_bfloat162*>(&outb[(size_t)r0 * CC + c]) =
                __floats2bfloat162_rn(acc[mi][ni][0], acc[mi][ni][1]);
            *reinterpret_cast<__nv_bfloat162*>(&outb[(size_t)(r0 + 8) * CC + c]) =
                __floats2bfloat162_rn(acc[mi][ni][2], acc[mi][ni][3]);
        }
}

// ---------------- gate GEMM (K=2C) + fused surprise epilogue -> upd ----------------
__global__ void __launch_bounds__(256) gemm_gate(const float* __restrict__ bg, int bm_base)
{
    extern __shared__ char smem_g[];
    const unsigned sbase = smem_u32(smem_g);
    const int tid = threadIdx.x, warp = tid >> 5, lane = tid & 31;
    const int wrow = (warp >> 2) * 64, wcol = (warp & 3) * 32;
    const int bm = bm_base + blockIdx.y * 128, bn = blockIdx.x * 128;

    float acc[4][4][4];
#pragma unroll
    for (int i = 0; i < 4; i++)
#pragma unroll
        for (int j = 0; j < 4; j++)
#pragma unroll
            for (int k = 0; k < 4; k++) acc[i][j][k] = 0.f;

    gemm_mainloop(g_retrb, g_pb, g_Wgb, 2 * CC, bm, bn, sbase, tid, wrow, wcol, lane, acc);

    const int g = lane >> 2, t = lane & 3;
#pragma unroll
    for (int mi = 0; mi < 4; mi++)
#pragma unroll
        for (int ni = 0; ni < 4; ni++) {
            int cl = wcol + ni * 8 + 2 * t;
            int gc = bn + cl;
            float e0 = g_etas[gc], e1 = g_etas[gc + 1];
            float b0 = bg[gc],     b1 = bg[gc + 1];
#pragma unroll
            for (int hh = 0; hh < 2; hh++) {
                int r = bm + wrow + mi * 16 + g + hh * 8;
                size_t gi = (size_t)r * CC + gc;
                float2 wv2 = __bfloat1622float2(
                    *reinterpret_cast<const __nv_bfloat162*>(&g_WVb[gi]));
                float2 rt2 = __bfloat1622float2(
                    *reinterpret_cast<const __nv_bfloat162*>(&g_retrb[gi]));
                float s0 = 1.f / (1.f + __expf(-(acc[mi][ni][hh*2+0] + b0)));
                float s1 = 1.f / (1.f + __expf(-(acc[mi][ni][hh*2+1] + b1)));
                *reinterpret_cast<float2*>(&g_upd[gi]) =
                    make_float2(e0 * s0 * (wv2.x - rt2.x), e1 * s1 * (wv2.y - rt2.y));
            }
        }
}

// ---------------- M update: M_new = M + ww_m * upd_c (one CTA per batch row) ----------------
__global__ void __launch_bounds__(256) mupd_kernel(
    const float* __restrict__ Mm, float* __restrict__ mnew, int b_base)
{
    const int b = b_base + blockIdx.x;
    __shared__ float us[CC];
    __shared__ float wws[NSLOT];
    const int tid = threadIdx.x;
    ((float2*)us)[tid] = ((const float2*)(g_upd + (size_t)b * CC))[tid];
    if (tid < NSLOT) wws[tid] = g_ww[(size_t)b * NSLOT + tid];
    __syncthreads();

    const float4* M4 = (const float4*)(Mm + (size_t)b * NSLOT * CC);
    float4* O4 = (float4*)(mnew + (size_t)b * NSLOT * CC);
#pragma unroll 4
    for (int idx = tid; idx < NSLOT * CC / 4; idx += 256) {
        const int m = idx >> 7, c4 = idx & 127;
        const float w = wws[m];
        float4 mv = __ldcs(M4 + idx);
        float4 u = ((const float4*)us)[c4];
        float4 o;
        o.x = mv.x + w * u.x;
        o.y = mv.y + w * u.y;
        o.z = mv.z + w * u.z;
        o.w = mv.w + w * u.w;
        __stcs(O4 + idx, o);
    }
}

// ---------------- fused attention / retrieval / Mk_new ----------------
__global__ void __launch_bounds__(256) attn_kernel(
    const float* __restrict__ h, const float* __restrict__ Mk,
    const float* __restrict__ Mm, float* __restrict__ out, int b_base)
{
    const int b = b_base + blockIdx.x;
    __shared__ float qs[CC], wks[CC];
    __shared__ float sm[NSLOT], tm[NSLOT], attnv[NSLOT], wws[NSLOT];

    const int tid = threadIdx.x;
    const int warp = tid >> 5, lane = tid & 31;
    const float* Mkb = Mk + (size_t)b * NSLOT * CC;
    const float* Mb  = Mm + (size_t)b * NSLOT * CC;

    {
        float2 q2 = __bfloat1622float2(((const __nv_bfloat162*)(g_Qb  + (size_t)b * CC))[tid]);
        float2 w2 = __bfloat1622float2(((const __nv_bfloat162*)(g_WKb + (size_t)b * CC))[tid]);
        qs [2*tid] = q2.x; qs [2*tid+1] = q2.y;
        wks[2*tid] = w2.x; wks[2*tid+1] = w2.y;
    }
    __syncthreads();

    // dual dot products vs M_keys rows (warp -> 4 slots)
#pragma unroll
    for (int mm = 0; mm < 4; mm++) {
        const int m = warp * 4 + mm;
        const float4* row4 = (const float4*)(Mkb + (size_t)m * CC);
        float s = 0.f, tt = 0.f;
#pragma unroll
        for (int it = 0; it < 4; it++) {
            float4 v = row4[lane + it * 32];
            float4 q = ((const float4*)qs)[lane + it * 32];
            float4 w = ((const float4*)wks)[lane + it * 32];
            s  += v.x*q.x + v.y*q.y + v.z*q.z + v.w*q.w;
            tt += v.x*w.x + v.y*w.y + v.z*w.z + v.w*w.w;
        }
#pragma unroll
        for (int o = 16; o > 0; o >>= 1) {
            s  += __shfl_xor_sync(0xffffffffu, s,  o);
            tt += __shfl_xor_sync(0xffffffffu, tt, o);
        }
        if (lane == 0) { sm[m] = s; tm[m] = tt; }
    }
    __syncthreads();

    if (tid < 32) {
        const float isq = 1.0f / sqrtf((float)CC);
        float s = sm[tid] * isq;
        float w = tm[tid] * isq;
        float mx = s;
#pragma unroll
        for (int o = 16; o > 0; o >>= 1) mx = fmaxf(mx, __shfl_xor_sync(0xffffffffu, mx, o));
        float e = expf(s - mx), sum = e;
#pragma unroll
        for (int o = 16; o > 0; o >>= 1) sum += __shfl_xor_sync(0xffffffffu, sum, o);
        attnv[tid] = e / sum;

        float mx2 = w;
#pragma unroll
        for (int o = 16; o > 0; o >>= 1) mx2 = fmaxf(mx2, __shfl_xor_sync(0xffffffffu, mx2, o));
        float e2 = expf(w - mx2), sum2 = e2;
#pragma unroll
        for (int o = 16; o > 0; o >>= 1) sum2 += __shfl_xor_sync(0xffffffffu, sum2, o);
        const float wv = e2 / sum2;
        wws[tid] = wv;
        g_ww[(size_t)b * NSLOT + tid] = wv;
    }
    __syncthreads();

    // Mk_new FIRST (Mk hot in L2 from the dot-product phase)
    {
        float* mkout = out + (size_t)BB * CC + (size_t)BB * NSLOT * CC + (size_t)b * NSLOT * CC;
        const float4* Mk4 = (const float4*)Mkb;
        float4* mo4 = (float4*)mkout;
        for (int idx = tid; idx < NSLOT * CC / 4; idx += 256) {
            const int m = idx >> 7;
            const int c4 = idx & 127;
            float4 mk = Mk4[idx];
            float4 wk = ((const float4*)wks)[c4];
            float w = wws[m] * 0.01f;
            float4 o;
            o.x = mk.x + w * (wk.x - mk.x);
            o.y = mk.y + w * (wk.y - mk.y);
            o.z = mk.z + w * (wk.z - mk.z);
            o.w = mk.w + w * (wk.w - mk.w);
            __stcs(mo4 + idx, o);
        }
    }

    // retrieval (streams M, evict-first) + out + bf16 retr for gate GEMM
    {
        const float2* M2 = (const float2*)Mb;
        float2 r = make_float2(0.f, 0.f);
#pragma unroll
        for (int m = 0; m < NSLOT; m++) {
            float2 v = __ldcs(M2 + m * (CC / 2) + tid);
            r.x += attnv[m] * v.x;
            r.y += attnv[m] * v.y;
        }
        const float2* h2 = (const float2*)(h + (size_t)b * CC);
        float2 hv = h2[tid];
        __stcs((float2*)(out + (size_t)b * CC) + tid, make_float2(hv.x + r.x, hv.y + r.y));
        __nv_bfloat162 rb = __floats2bfloat162_rn(r.x, r.y);
        ((__nv_bfloat162*)(g_retrb + (size_t)b * CC))[tid] = rb;
    }
}

// ---------------- launch: serial DRAM backbone, tensor-only overlap on s1 ----------------
extern "C" void kernel_launch(void* const* d_in, const int* in_sizes, int n_in,
                              void* d_out, int out_size)
{
    const float* h   = (const float*)d_in[0];
    const float* p   = (const float*)d_in[1];
    const float* M   = (const float*)d_in[2];
    const float* Mk  = (const float*)d_in[3];
    const float* Wq  = (const float*)d_in[4];
    const float* Wk  = (const float*)d_in[5];
    const float* Wv  = (const float*)d_in[6];
    const float* Wg  = (const float*)d_in[7];
    const float* bg  = (const float*)d_in[8];
    const float* eta = (const float*)d_in[9];
    float* out = (float*)d_out;
    float* mnew = out + (size_t)BB * CC;

    static cudaStream_t s1 = nullptr;
    static cudaEvent_t evC, evA0, evA1, evGA, evGB;
    if (s1 == nullptr) {
        cudaFuncSetAttribute(gemm_proj, cudaFuncAttributeMaxDynamicSharedMemorySize, 61440);
        cudaFuncSetAttribute(gemm_gate, cudaFuncAttributeMaxDynamicSharedMemorySize, 61440);
        cudaStreamCreateWithFlags(&s1, cudaStreamNonBlocking);
        cudaEventCreateWithFlags(&evC,  cudaEventDisableTiming);
        cudaEventCreateWithFlags(&evA0, cudaEventDisableTiming);
        cudaEventCreateWithFlags(&evA1, cudaEventDisableTiming);
        cudaEventCreateWithFlags(&evGA, cudaEventDisableTiming);
        cudaEventCreateWithFlags(&evGB, cudaEventDisableTiming);
    }

    // front (s0): bf16 conversion (+ eta sigmoid), then Q/WK projections
    convert_kernel<<<9472, 256>>>(h, p, Wq, Wk, Wv, Wg, eta);
    cudaEventRecord(evC, 0);
    gemm_proj<<<dim3(4, 64, 2), 256, 61440>>>(0);          // Q, WK (full batch)

    // s1: WV projection (tensor-bound) overlapped with attnA
    cudaStreamWaitEvent(s1, evC, 0);
    gemm_proj<<<dim3(4, 64, 1), 256, 61440, s1>>>(2);      // WV (full batch)

    // s0: attention halves (DRAM backbone — never co-run with streaming kernels)
    attn_kernel<<<HB, 256>>>(h, Mk, M, out, 0);
    cudaEventRecord(evA0, 0);
    attn_kernel<<<HB, 256>>>(h, Mk, M, out, HB);
    cudaEventRecord(evA1, 0);

    // s1: gate halves (tensor-bound); gateA under attnB, gateB under mupdA
    cudaStreamWaitEvent(s1, evA0, 0);
    gemm_gate<<<dim3(4, HB / 128), 256, 61440, s1>>>(bg, 0);
    cudaEventRecord(evGA, s1);
    cudaStreamWaitEvent(s1, evA1, 0);
    gemm_gate<<<dim3(4, HB / 128), 256, 61440, s1>>>(bg, HB);
    cudaEventRecord(evGB, s1);

    // s0: M_new streaming halves (serial on the DRAM backbone)
    cudaStreamWaitEvent(0, evGA, 0);
    mupd_kernel<<<HB, 256>>>(M, mnew, 0);
    cudaStreamWaitEvent(0, evGB, 0);   // also joins s1 back for capture
    mupd_kernel<<<HB, 256>>>(M, mnew, HB);
}

// round 14
// speedup vs baseline: 1.1084x; 1.0427x over previous
#include <cuda_runtime.h>
#include <cuda_bf16.h>
#include <math.h>

#define BB 8192
#define CC 512
#define NSLOT 32
#define HB 4096   // rows per half

// ---------------- scratch (no allocations allowed) ----------------
__device__ float g_upd [BB*CC];
__device__ float g_ww  [BB*NSLOT];
__device__ float g_etas[CC];
__device__ __nv_bfloat16 g_Qb   [BB*CC];
__device__ __nv_bfloat16 g_WKb  [BB*CC];
__device__ __nv_bfloat16 g_WVb  [BB*CC];
__device__ __nv_bfloat16 g_hb   [BB*CC];
__device__ __nv_bfloat16 g_pb   [BB*CC];
__device__ __nv_bfloat16 g_retrb[BB*CC];
__device__ __nv_bfloat16 g_Wqb  [CC*CC];
__device__ __nv_bfloat16 g_Wkb  [CC*CC];
__device__ __nv_bfloat16 g_Wvb  [CC*CC];
__device__ __nv_bfloat16 g_Wgb  [2*CC*CC];

// ---------------- helpers ----------------
__device__ __forceinline__ uint2 cvt4(float4 v) {
    __nv_bfloat162 lo = __floats2bfloat162_rn(v.x, v.y);
    __nv_bfloat162 hi = __floats2bfloat162_rn(v.z, v.w);
    uint2 r;
    r.x = *reinterpret_cast<unsigned int*>(&lo);
    r.y = *reinterpret_cast<unsigned int*>(&hi);
    return r;
}

__device__ __forceinline__ unsigned smem_u32(const void* p) {
    unsigned a;
    asm volatile("{ .reg .u64 t; cvta.to.shared.u64 t, %1; cvt.u32.u64 %0, t; }"
                 : "=r"(a) : "l"(p));
    return a;
}

__device__ __forceinline__ void cp16(unsigned dst, const void* src) {
    asm volatile("cp.async.cg.shared.global [%0], [%1], 16;" :: "r"(dst), "l"(src));
}
#define CP_COMMIT() asm volatile("cp.async.commit_group;" ::)
#define CP_WAIT1()  asm volatile("cp.async.wait_group 1;" ::)
#define CP_WAIT0()  asm volatile("cp.async.wait_group 0;" ::)

__device__ __forceinline__ void ldsm4(unsigned* r, unsigned a) {
    asm volatile("ldmatrix.sync.aligned.m8n8.x4.shared.b16 {%0,%1,%2,%3}, [%4];"
                 : "=r"(r[0]), "=r"(r[1]), "=r"(r[2]), "=r"(r[3]) : "r"(a));
}

__device__ __forceinline__ void mma16816(float* d, const unsigned* a, const unsigned* b) {
    asm volatile(
        "mma.sync.aligned.m16n8k16.row.col.f32.bf16.bf16.f32 "
        "{%0,%1,%2,%3}, {%4,%5,%6,%7}, {%8,%9}, {%0,%1,%2,%3};\n"
        : "+f"(d[0]), "+f"(d[1]), "+f"(d[2]), "+f"(d[3])
        : "r"(a[0]), "r"(a[1]), "r"(a[2]), "r"(a[3]), "r"(b[0]), "r"(b[1]));
}

// ---------------- one-shot bf16 conversion ----------------
__global__ void __launch_bounds__(256) convert_kernel(
    const float* __restrict__ h, const float* __restrict__ p,
    const float* __restrict__ Wq, const float* __restrict__ Wk,
    const float* __restrict__ Wv, const float* __restrict__ Wg,
    const float* __restrict__ eta)
{
    if (blockIdx.x == 0 && threadIdx.x < 256) {
        for (int c = threadIdx.x; c < CC; c += 256)
            g_etas[c] = 1.f / (1.f + __expf(-eta[c]));
    }
    int i = blockIdx.x * 256 + threadIdx.x;
    const float4* src; __nv_bfloat16* dst; int off;
    if      (i < 1048576) { src = (const float4*)h;  dst = g_hb;  off = 0;       }
    else if (i < 2097152) { src = (const float4*)p;  dst = g_pb;  off = 1048576; }
    else if (i < 2162688) { src = (const float4*)Wq; dst = g_Wqb; off = 2097152; }
    else if (i < 2228224) { src = (const float4*)Wk; dst = g_Wkb; off = 2162688; }
    else if (i < 2293760) { src = (const float4*)Wv; dst = g_Wvb; off = 2228224; }
    else                  { src = (const float4*)Wg; dst = g_Wgb; off = 2293760; }
    int j = i - off;
    *reinterpret_cast<uint2*>(dst + 4 * (size_t)j) = cvt4(src[j]);
}

// ---------------- GEMM mainloop BM=128 (projections) ----------------
__device__ __forceinline__ void gemm_mainloop(
    const __nv_bfloat16* A0,
    const __nv_bfloat16* W, int K, int bm, int bn,
    unsigned sbase, int tid, int wrow, int wcol, int lane,
    float acc[4][4][4])
{
    const int KT = K / 32;
#pragma unroll
    for (int pre = 0; pre < 2; pre++) {
        const int k0 = pre * 32;
        const unsigned as = sbase + pre * 10240;
        const unsigned bs = sbase + 30720 + pre * 10240;
#pragma unroll
        for (int i = 0; i < 2; i++) {
            int slot = tid + i * 256;
            int row = slot >> 2, ch = slot & 3;
            cp16(as + row * 80 + ch * 16, A0 + (size_t)(bm + row) * CC + k0 + ch * 8);
            cp16(bs + row * 80 + ch * 16, W + (size_t)(bn + row) * K + k0 + ch * 8);
        }
        CP_COMMIT();
    }

    for (int kt = 0; kt < KT; kt++) {
        CP_WAIT1();
        __syncthreads();
        const unsigned as = sbase + (kt % 3) * 10240;
        const unsigned bs = sbase + 30720 + (kt % 3) * 10240;
#pragma unroll
        for (int ks = 0; ks < 2; ks++) {
            unsigned a[4][4], b[4][2], r[4];
#pragma unroll
            for (int mi = 0; mi < 4; mi++)
                ldsm4(a[mi], as + (unsigned)((wrow + mi * 16 + (lane & 15)) * 80
                                             + (2 * ks + (lane >> 4)) * 16));
#pragma unroll
            for (int pp = 0; pp < 2; pp++) {
                ldsm4(r, bs + (unsigned)((wcol + pp * 16 + (lane & 7) + ((lane >> 4) << 3)) * 80
                                         + (2 * ks + ((lane >> 3) & 1)) * 16));
                b[2*pp][0] = r[0]; b[2*pp][1] = r[1];
                b[2*pp+1][0] = r[2]; b[2*pp+1][1] = r[3];
            }
#pragma unroll
            for (int mi = 0; mi < 4; mi++)
#pragma unroll
                for (int ni = 0; ni < 4; ni++)
                    mma16816(acc[mi][ni], a[mi], b[ni]);
        }
        if (kt + 2 < KT) {
            const int k2 = kt + 2, k0 = k2 * 32;
            const unsigned as2 = sbase + (k2 % 3) * 10240;
            const unsigned bs2 = sbase + 30720 + (k2 % 3) * 10240;
#pragma unroll
            for (int i = 0; i < 2; i++) {
                int slot = tid + i * 256;
                int row = slot >> 2, ch = slot & 3;
                cp16(as2 + row * 80 + ch * 16, A0 + (size_t)(bm + row) * CC + k0 + ch * 8);
                cp16(bs2 + row * 80 + ch * 16, W + (size_t)(bn + row) * K + k0 + ch * 8);
            }
        }
        CP_COMMIT();
    }
    CP_WAIT0();
    __syncthreads();
}

// ---------------- projections: z in {0:Q, 1:WK, 2:WV} via zoff ----------------
__global__ void __launch_bounds__(256) gemm_proj(int zoff, int bm_base)
{
    extern __shared__ char smem_p[];
    const unsigned sbase = smem_u32(smem_p);
    const int tid = threadIdx.x, warp = tid >> 5, lane = tid & 31;
    const int wrow = (warp >> 2) * 64, wcol = (warp & 3) * 32;
    const int bm = bm_base + blockIdx.y * 128, bn = blockIdx.x * 128;
    const int z = blockIdx.z + zoff;

    const __nv_bfloat16* A = (z == 0) ? g_hb : g_pb;
    const __nv_bfloat16* W = (z == 0) ? g_Wqb : ((z == 1) ? g_Wkb : g_Wvb);
    __nv_bfloat16* outb = (z == 0) ? g_Qb : ((z == 1) ? g_WKb : g_WVb);

    float acc[4][4][4];
#pragma unroll
    for (int i = 0; i < 4; i++)
#pragma unroll
        for (int j = 0; j < 4; j++)
#pragma unroll
            for (int k = 0; k < 4; k++) acc[i][j][k] = 0.f;

    gemm_mainloop(A, W, CC, bm, bn, sbase, tid, wrow, wcol, lane, acc);

    const int g = lane >> 2, t = lane & 3;
#pragma unroll
    for (int mi = 0; mi < 4; mi++)
#pragma unroll
        for (int ni = 0; ni < 4; ni++) {
            int r0 = bm + wrow + mi * 16 + g;
            int c  = bn + wcol + ni * 8 + 2 * t;
            *reinterpret_cast<__nv_bfloat162*>(&outb[(size_t)r0 * CC + c]) =
                __floats2bfloat162_rn(acc[mi][ni][0], acc[mi][ni][1]);
            *reinterpret_cast<__nv_bfloat162*>(&outb[(size_t)(r0 + 8) * CC + c]) =
                __floats2bfloat162_rn(acc[mi][ni][2], acc[mi][ni][3]);
        }
}

// ---------------- gate GEMM: BM=64, BN=128, K=2C concat A ----------------
// A stages 64*80=5120B x3 at sbase; B stages 10240B x3 at sbase+15360. Total 46080B.
__global__ void __launch_bounds__(256) gemm_gate(const float* __restrict__ bg, int bm_base)
{
    extern __shared__ char smem_g[];
    const unsigned sbase = smem_u32(smem_g);
    const int tid = threadIdx.x, warp = tid >> 5, lane = tid & 31;
    const int wrow = (warp >> 2) * 32, wcol = (warp & 3) * 32;
    const int bm = bm_base + blockIdx.y * 64, bn = blockIdx.x * 128;
    const int K = 2 * CC;

    float acc[2][4][4];
#pragma unroll
    for (int i = 0; i < 2; i++)
#pragma unroll
        for (int j = 0; j < 4; j++)
#pragma unroll
            for (int k = 0; k < 4; k++) acc[i][j][k] = 0.f;

    const int KT = K / 32;
#pragma unroll
    for (int pre = 0; pre < 2; pre++) {
        const int k0 = pre * 32;
        const __nv_bfloat16* Ab = (k0 >= CC) ? (g_pb + (k0 - CC)) : (g_retrb + k0);
        const unsigned as = sbase + pre * 5120;
        const unsigned bs = sbase + 15360 + pre * 10240;
        {
            int row = tid >> 2, ch = tid & 3;
            cp16(as + row * 80 + ch * 16, Ab + (size_t)(bm + row) * CC + ch * 8);
        }
#pragma unroll
        for (int i = 0; i < 2; i++) {
            int slot = tid + i * 256;
            int row = slot >> 2, ch = slot & 3;
            cp16(bs + row * 80 + ch * 16, g_Wgb + (size_t)(bn + row) * K + k0 + ch * 8);
        }
        CP_COMMIT();
    }

    for (int kt = 0; kt < KT; kt++) {
        CP_WAIT1();
        __syncthreads();
        const unsigned as = sbase + (kt % 3) * 5120;
        const unsigned bs = sbase + 15360 + (kt % 3) * 10240;
#pragma unroll
        for (int ks = 0; ks < 2; ks++) {
            unsigned a[2][4], b[4][2], r[4];
#pragma unroll
            for (int mi = 0; mi < 2; mi++)
                ldsm4(a[mi], as + (unsigned)((wrow + mi * 16 + (lane & 15)) * 80
                                             + (2 * ks + (lane >> 4)) * 16));
#pragma unroll
            for (int pp = 0; pp < 2; pp++) {
                ldsm4(r, bs + (unsigned)((wcol + pp * 16 + (lane & 7) + ((lane >> 4) << 3)) * 80
                                         + (2 * ks + ((lane >> 3) & 1)) * 16));
                b[2*pp][0] = r[0]; b[2*pp][1] = r[1];
                b[2*pp+1][0] = r[2]; b[2*pp+1][1] = r[3];
            }
#pragma unroll
            for (int mi = 0; mi < 2; mi++)
#pragma unroll
                for (int ni = 0; ni < 4; ni++)
                    mma16816(acc[mi][ni], a[mi], b[ni]);
        }
        if (kt + 2 < KT) {
            const int k2 = kt + 2, k0 = k2 * 32;
            const __nv_bfloat16* Ab = (k0 >= CC) ? (g_pb + (k0 - CC)) : (g_retrb + k0);
            const unsigned as2 = sbase + (k2 % 3) * 5120;
            const unsigned bs2 = sbase + 15360 + (k2 % 3) * 10240;
            {
                int row = tid >> 2, ch = tid & 3;
                cp16(as2 + row * 80 + ch * 16, Ab + (size_t)(bm + row) * CC + ch * 8);
            }
#pragma unroll
            for (int i = 0; i < 2; i++) {
                int slot = tid + i * 256;
                int row = slot >> 2, ch = slot & 3;
                cp16(bs2 + row * 80 + ch * 16, g_Wgb + (size_t)(bn + row) * K + k0 + ch * 8);
            }
        }
        CP_COMMIT();
    }
    CP_WAIT0();
    __syncthreads();

    const int g = lane >> 2, t = lane & 3;
#pragma unroll
    for (int mi = 0; mi < 2; mi++)
#pragma unroll
        for (int ni = 0; ni < 4; ni++) {
            int cl = wcol + ni * 8 + 2 * t;
            int gc = bn + cl;
            float e0 = g_etas[gc], e1 = g_etas[gc + 1];
            float b0 = bg[gc],     b1 = bg[gc + 1];
#pragma unroll
            for (int hh = 0; hh < 2; hh++) {
                int r = bm + wrow + mi * 16 + g + hh * 8;
                size_t gi = (size_t)r * CC + gc;
                float2 wv2 = __bfloat1622float2(
                    *reinterpret_cast<const __nv_bfloat162*>(&g_WVb[gi]));
                float2 rt2 = __bfloat1622float2(
                    *reinterpret_cast<const __nv_bfloat162*>(&g_retrb[gi]));
                float s0 = 1.f / (1.f + __expf(-(acc[mi][ni][hh*2+0] + b0)));
                float s1 = 1.f / (1.f + __expf(-(acc[mi][ni][hh*2+1] + b1)));
                *reinterpret_cast<float2*>(&g_upd[gi]) =
                    make_float2(e0 * s0 * (wv2.x - rt2.x), e1 * s1 * (wv2.y - rt2.y));
            }
        }
}

// ---------------- M update: M_new = M + ww_m * upd_c (one CTA per batch row) ----------------
__global__ void __launch_bounds__(256) mupd_kernel(
    const float* __restrict__ Mm, float* __restrict__ mnew, int b_base)
{
    const int b = b_base + blockIdx.x;
    __shared__ __align__(16) float us[CC];
    __shared__ float wws[NSLOT];
    const int tid = threadIdx.x;
    ((float2*)us)[tid] = ((const float2*)(g_upd + (size_t)b * CC))[tid];
    if (tid < NSLOT) wws[tid] = g_ww[(size_t)b * NSLOT + tid];
    __syncthreads();

    const float4* M4 = (const float4*)(Mm + (size_t)b * NSLOT * CC);
    float4* O4 = (float4*)(mnew + (size_t)b * NSLOT * CC);
#pragma unroll 4
    for (int idx = tid; idx < NSLOT * CC / 4; idx += 256) {
        const int m = idx >> 7, c4 = idx & 127;
        const float w = wws[m];
        float4 mv = __ldcs(M4 + idx);
        float4 u = ((const float4*)us)[c4];
        float4 o;
        o.x = mv.x + w * u.x;
        o.y = mv.y + w * u.y;
        o.z = mv.z + w * u.z;
        o.w = mv.w + w * u.w;
        __stcs(O4 + idx, o);
    }
}

// ---------------- fused attention / retrieval / Mk_new ----------------
__global__ void __launch_bounds__(256) attn_kernel(
    const float* __restrict__ h, const float* __restrict__ Mk,
    const float* __restrict__ Mm, float* __restrict__ out, int b_base)
{
    const int b = b_base + blockIdx.x;
    __shared__ __align__(16) float qs[CC], wks[CC];
    __shared__ __align__(16) float part[2][CC];
    __shared__ float sm[NSLOT], tm[NSLOT], attnv[NSLOT], wws[NSLOT];

    const int tid = threadIdx.x;
    const int warp = tid >> 5, lane = tid & 31;
    const float* Mkb = Mk + (size_t)b * NSLOT * CC;
    const float* Mb  = Mm + (size_t)b * NSLOT * CC;

    {
        float2 q2 = __bfloat1622float2(((const __nv_bfloat162*)(g_Qb  + (size_t)b * CC))[tid]);
        float2 w2 = __bfloat1622float2(((const __nv_bfloat162*)(g_WKb + (size_t)b * CC))[tid]);
        qs [2*tid] = q2.x; qs [2*tid+1] = q2.y;
        wks[2*tid] = w2.x; wks[2*tid+1] = w2.y;
    }
    __syncthreads();

    // dual dot products vs M_keys (warp -> 4 slots), loads interleaved across slots
    {
        const float4* Mk4r = (const float4*)Mkb;
        float s4[4] = {0.f, 0.f, 0.f, 0.f}, t4[4] = {0.f, 0.f, 0.f, 0.f};
#pragma unroll
        for (int it = 0; it < 4; it++) {
            float4 q = ((const float4*)qs)[lane + it * 32];
            float4 w = ((const float4*)wks)[lane + it * 32];
#pragma unroll
            for (int mm = 0; mm < 4; mm++) {
                float4 v = Mk4r[(warp * 4 + mm) * 128 + lane + it * 32];
                s4[mm] += v.x*q.x + v.y*q.y + v.z*q.z + v.w*q.w;
                t4[mm] += v.x*w.x + v.y*w.y + v.z*w.z + v.w*w.w;
            }
        }
#pragma unroll
        for (int mm = 0; mm < 4; mm++) {
            float s = s4[mm], tt = t4[mm];
#pragma unroll
            for (int o = 16; o > 0; o >>= 1) {
                s  += __shfl_xor_sync(0xffffffffu, s,  o);
                tt += __shfl_xor_sync(0xffffffffu, tt, o);
            }
            if (lane == 0) { sm[warp * 4 + mm] = s; tm[warp * 4 + mm] = tt; }
        }
    }
    __syncthreads();

    if (tid < 32) {
        const float isq = 1.0f / sqrtf((float)CC);
        float s = sm[tid] * isq;
        float w = tm[tid] * isq;
        float mx = s;
#pragma unroll
        for (int o = 16; o > 0; o >>= 1) mx = fmaxf(mx, __shfl_xor_sync(0xffffffffu, mx, o));
        float e = expf(s - mx), sum = e;
#pragma unroll
        for (int o = 16; o > 0; o >>= 1) sum += __shfl_xor_sync(0xffffffffu, sum, o);
        attnv[tid] = e / sum;

        float mx2 = w;
#pragma unroll
        for (int o = 16; o > 0; o >>= 1) mx2 = fmaxf(mx2, __shfl_xor_sync(0xffffffffu, mx2, o));
        float e2 = expf(w - mx2), sum2 = e2;
#pragma unroll
        for (int o = 16; o > 0; o >>= 1) sum2 += __shfl_xor_sync(0xffffffffu, sum2, o);
        const float wv = e2 / sum2;
        wws[tid] = wv;
        g_ww[(size_t)b * NSLOT + tid] = wv;
    }
    __syncthreads();

    // Mk_new (Mk hot in L2 from dot phase)
    {
        float* mkout = out + (size_t)BB * CC + (size_t)BB * NSLOT * CC + (size_t)b * NSLOT * CC;
        const float4* Mk4 = (const float4*)Mkb;
        float4* mo4 = (float4*)mkout;
#pragma unroll 4
        for (int idx = tid; idx < NSLOT * CC / 4; idx += 256) {
            const int m = idx >> 7;
            const int c4 = idx & 127;
            float4 mk = Mk4[idx];
            float4 wk = ((const float4*)wks)[c4];
            float w = wws[m] * 0.01f;
            float4 o;
            o.x = mk.x + w * (wk.x - mk.x);
            o.y = mk.y + w * (wk.y - mk.y);
            o.z = mk.z + w * (wk.z - mk.z);
            o.w = mk.w + w * (wk.w - mk.w);
            __stcs(mo4 + idx, o);
        }
    }

    // retrieval: 2 groups x 128 threads, 16 slots each, float4 streaming loads
    {
        const int grp = tid >> 7, ct = tid & 127;
        const float4* M4 = (const float4*)Mb;
        float4 r = make_float4(0.f, 0.f, 0.f, 0.f);
#pragma unroll
        for (int m = 0; m < 16; m++) {
            const int slot = grp * 16 + m;
            const float a = attnv[slot];
            float4 v = __ldcs(M4 + slot * 128 + ct);
            r.x += a * v.x; r.y += a * v.y; r.z += a * v.z; r.w += a * v.w;
        }
        ((float4*)part[grp])[ct] = r;
        __syncthreads();
        if (grp == 0) {
            float4 r0 = ((float4*)part[0])[ct];
            float4 r1 = ((float4*)part[1])[ct];
            float4 rr = make_float4(r0.x + r1.x, r0.y + r1.y, r0.z + r1.z, r0.w + r1.w);
            const float4* h4 = (const float4*)(h + (size_t)b * CC);
            float4 hv = h4[ct];
            __stcs((float4*)(out + (size_t)b * CC) + ct,
                   make_float4(hv.x + rr.x, hv.y + rr.y, hv.z + rr.z, hv.w + rr.w));
            *reinterpret_cast<uint2*>(g_retrb + (size_t)b * CC + ct * 4) = cvt4(rr);
        }
    }
}

// ---------------- launch ----------------
extern "C" void kernel_launch(void* const* d_in, const int* in_sizes, int n_in,
                              void* d_out, int out_size)
{
    const float* h   = (const float*)d_in[0];
    const float* p   = (const float*)d_in[1];
    const float* M   = (const float*)d_in[2];
    const float* Mk  = (const float*)d_in[3];
    const float* Wq  = (const float*)d_in[4];
    const float* Wk  = (const float*)d_in[5];
    const float* Wv  = (const float*)d_in[6];
    const float* Wg  = (const float*)d_in[7];
    const float* bg  = (const float*)d_in[8];
    const float* eta = (const float*)d_in[9];
    float* out = (float*)d_out;
    float* mnew = out + (size_t)BB * CC;

    static cudaStream_t s1 = nullptr;
    static cudaEvent_t evC, evP1, evA0, evA1, evGA, evGB;
    if (s1 == nullptr) {
        cudaFuncSetAttribute(gemm_proj, cudaFuncAttributeMaxDynamicSharedMemorySize, 61440);
        cudaFuncSetAttribute(gemm_gate, cudaFuncAttributeMaxDynamicSharedMemorySize, 46080);
        cudaStreamCreateWithFlags(&s1, cudaStreamNonBlocking);
        cudaEventCreateWithFlags(&evC,  cudaEventDisableTiming);
        cudaEventCreateWithFlags(&evP1, cudaEventDisableTiming);
        cudaEventCreateWithFlags(&evA0, cudaEventDisableTiming);
        cudaEventCreateWithFlags(&evA1, cudaEventDisableTiming);
        cudaEventCreateWithFlags(&evGA, cudaEventDisableTiming);
        cudaEventCreateWithFlags(&evGB, cudaEventDisableTiming);
    }

    // front (s0): conversion, then Q/WK projections for half A only
    convert_kernel<<<9472, 256>>>(h, p, Wq, Wk, Wv, Wg, eta);
    cudaEventRecord(evC, 0);
    gemm_proj<<<dim3(4, HB / 128, 2), 256, 61440>>>(0, 0);      // Q,WK half A

    // s1: Q/WK half B, then WV full batch (tensor work under attnA)
    cudaStreamWaitEvent(s1, evC, 0);
    gemm_proj<<<dim3(4, HB / 128, 2), 256, 61440, s1>>>(0, HB); // Q,WK half B
    cudaEventRecord(evP1, s1);
    gemm_proj<<<dim3(4, 64, 1), 256, 61440, s1>>>(2, 0);        // WV full

    // s0: attention halves (DRAM backbone)
    attn_kernel<<<HB, 256>>>(h, Mk, M, out, 0);
    cudaEventRecord(evA0, 0);
    cudaStreamWaitEvent(0, evP1, 0);
    attn_kernel<<<HB, 256>>>(h, Mk, M, out, HB);
    cudaEventRecord(evA1, 0);

    // s1: gate halves (BM=64, light footprint); gateA under attnB, gateB under mupdA
    cudaStreamWaitEvent(s1, evA0, 0);
    gemm_gate<<<dim3(4, HB / 64), 256, 46080, s1>>>(bg, 0);
    cudaEventRecord(evGA, s1);
    cudaStreamWaitEvent(s1, evA1, 0);
    gemm_gate<<<dim3(4, HB / 64), 256, 46080, s1>>>(bg, HB);
    cudaEventRecord(evGB, s1);

    // s0: M_new streaming halves
    cudaStreamWaitEvent(0, evGA, 0);
    mupd_kernel<<<HB, 256>>>(M, mnew, 0);
    cudaStreamWaitEvent(0, evGB, 0);   // joins s1 for capture
    mupd_kernel<<<HB, 256>>>(M, mnew, HB);
}